// round 15
// baseline (speedup 1.0000x reference)
#include <cuda_runtime.h>
#include <cuda_bf16.h>
#include <cuda_fp16.h>
#include <math.h>
#include <stdint.h>

// Problem constants
#define SS 1024   // sequence length S
#define BB 32     // batch B
#define DD 1024   // model dim D

// Pipeline groups: 4 groups x 8 batches on {default, s1, s2, s3}
#define NGRP 4
#define GB (BB / NGRP)   // 8

// GEMM tiling: 128x128 block tile, 2 CTAs/SM (reg-capped), 2-stage cp.async
#define MT 128
#define NT 128
#define BK 64
#define AST 72                        // smem row stride (halves)
#define A_HALVES (128 * AST)
#define B_HALVES (128 * AST)
#define BUF_HALVES (A_HALVES + B_HALVES)
#define GEMM_SMEM (2 * BUF_HALVES * 2)   // 73728 bytes

// Scratch (device globals — allocation-guard-safe)
__device__ __half g_probH[(size_t)BB * SS * SS];   // (B, r, c) compacted prob, fp16
__device__ __half g_peT[(size_t)BB * DD * SS];     // (B, d, c) compacted gathered pe, fp16
__device__ int   g_idx[BB * SS];                   // per-batch valid positions
__device__ int   g_inv[BB * SS];                   // per-batch invalid positions
__device__ int   g_nv[BB];                         // per-batch valid count

__device__ __forceinline__ uint32_t smem_u32(const void* p) {
    uint32_t a;
    asm("{ .reg .u64 t; cvta.to.shared.u64 t, %1; cvt.u32.u64 %0, t; }"
        : "=r"(a) : "l"(p));
    return a;
}
#define CP_ASYNC16(dst, src) \
    asm volatile("cp.async.cg.shared.global [%0], [%1], 16;" :: "r"(dst), "l"(src))
#define CP_COMMIT() asm volatile("cp.async.commit_group;" ::: "memory")
#define CP_WAIT(n)  asm volatile("cp.async.wait_group %0;" :: "n"(n) : "memory")
#define LDSM4(r0, r1, r2, r3, a) \
    asm volatile("ldmatrix.sync.aligned.m8n8.x4.shared.b16 {%0,%1,%2,%3}, [%4];" \
                 : "=r"(r0), "=r"(r1), "=r"(r2), "=r"(r3) : "r"(a))

// ---------------------------------------------------------------------------
// K0: mask kernel — inline dtype sniff + dual compaction (valid + invalid).
// ---------------------------------------------------------------------------
__global__ __launch_bounds__(1024) void mask_kernel(const void* __restrict__ maskp) {
    int b = blockIdx.x;
    int j = threadIdx.x;
    int lane = j & 31;
    int w    = j >> 5;

    const int* m32 = (const int*)maskp;
    int any = 0;
#pragma unroll
    for (int t = 0; t < 8; t++) {
        any |= ((unsigned)m32[t * 1024 + j] > 1u) ? 1 : 0;
    }
    int is_u8 = __syncthreads_or(any);

    int mv;
    if (is_u8) mv = ((const unsigned char*)maskp)[b * SS + j];
    else       mv = m32[b * SS + j];
    int valid = (mv == 0) ? 1 : 0;

    unsigned ball = __ballot_sync(0xFFFFFFFFu, valid);
    int rank = __popc(ball & ((1u << lane) - 1));
    int wcnt = __popc(ball);

    __shared__ int wsum[32];
    if (lane == 0) wsum[w] = wcnt;
    __syncthreads();
    if (j < 32) {
        int v = wsum[j];
#pragma unroll
        for (int o = 1; o < 32; o <<= 1) {
            int t = __shfl_up_sync(0xFFFFFFFFu, v, o);
            if (lane >= o) v += t;
        }
        wsum[j] = v;
    }
    __syncthreads();
    int base = (w == 0) ? 0 : wsum[w - 1];
    int vex  = base + rank;
    if (valid) g_idx[b * SS + vex] = j;
    else       g_inv[b * SS + (j - vex)] = j;

    if (j == 0) g_nv[b] = wsum[31];
}

// ---------------------------------------------------------------------------
// K0b: zero-fill invalid output rows via compacted invalid list.
// ---------------------------------------------------------------------------
__global__ __launch_bounds__(1024) void zerofill_kernel(float* __restrict__ out, int b0) {
    int b = b0 + blockIdx.y;
    int ninv = SS - g_nv[b];
    int r = blockIdx.x * 4 + (threadIdx.x >> 8);
    if (r >= ninv) return;
    int i = g_inv[b * SS + r];
    int c = (threadIdx.x & 255) * 4;
    *(float4*)(out + (size_t)i * (BB * DD) + (size_t)b * DD + c) =
        make_float4(0.f, 0.f, 0.f, 0.f);
}

// ---------------------------------------------------------------------------
// K1: fused pred + prob. Block (r, gb): r-th valid output row of batch b0+gb.
// ---------------------------------------------------------------------------
__global__ __launch_bounds__(256) void probpred_kernel(
    const float* __restrict__ x, const float* __restrict__ W,
    const float* __restrict__ bias, int b0)
{
    int r = blockIdx.x;
    int b = b0 + blockIdx.y;
    int nv = g_nv[b];
    if (r >= nv) return;
    int tid = threadIdx.x;

    const int* idxp = g_idx + b * SS;
    int i = idxp[r];

    float4 xa = ((const float4*)(x + ((size_t)i * BB + b) * DD))[tid];
    float4 wa = ((const float4*)W)[tid];
    float ds = xa.x * wa.x + xa.y * wa.y + xa.z * wa.z + xa.w * wa.w;

    __shared__ float red[8];
    __shared__ float s_bcast;
#pragma unroll
    for (int o = 16; o; o >>= 1) ds += __shfl_xor_sync(0xFFFFFFFFu, ds, o);
    if ((tid & 31) == 0) red[tid >> 5] = ds;
    __syncthreads();
    if (tid == 0) {
        float s = 0.0f;
#pragma unroll
        for (int wq = 0; wq < 8; wq++) s += red[wq];
        float p = 1.0f / (1.0f + expf(-(s + bias[0])));
        s_bcast = p * (float)nv + (float)(SS - nv);   // c0 = pred*slen + lang
    }
    __syncthreads();
    float c0 = s_bcast;
    __syncthreads();

    int4 ii = ((const int4*)idxp)[tid];
    float v[4];
    float lsum = 0.0f;
#pragma unroll
    for (int t = 0; t < 4; t++) {
        int cpos = 4 * tid + t;
        int jj = (t == 0) ? ii.x : (t == 1) ? ii.y : (t == 2) ? ii.z : ii.w;
        float val = 0.0f;
        if (cpos < nv) {
            float d = c0 - (float)jj;
            val = __fdividef(1.0f, d * d + 0.001f);
        }
        v[t] = val;
        lsum += val;
    }

#pragma unroll
    for (int o = 16; o; o >>= 1) lsum += __shfl_xor_sync(0xFFFFFFFFu, lsum, o);
    if ((tid & 31) == 0) red[tid >> 5] = lsum;
    __syncthreads();
    if (tid == 0) {
        float s = 0.0f;
#pragma unroll
        for (int wq = 0; wq < 8; wq++) s += red[wq];
        s_bcast = __fdividef(1.0f, s);
    }
    __syncthreads();
    float scale = s_bcast;

    __half h[4];
#pragma unroll
    for (int t = 0; t < 4; t++) h[t] = __float2half_rn(v[t] * scale);
    *(uint2*)(g_probH + ((size_t)b * SS + r) * SS + 4 * tid) = *(uint2*)h;
}

// ---------------------------------------------------------------------------
// K2: gather+transpose pe: peTc[b][d][c] = pe[idx[b][c], b, d] (fp16).
// ---------------------------------------------------------------------------
__global__ __launch_bounds__(256) void gather_kernel(const float* __restrict__ pe, int b0) {
    int c0 = blockIdx.x * 64;
    int d0 = blockIdx.y * 64;
    int b  = b0 + blockIdx.z;
    int nv = g_nv[b];
    int kceil = ((nv + BK - 1) / BK) * BK;
    if (c0 >= kceil) return;
    int tid = threadIdx.x;

    __shared__ float t[64][65];

#pragma unroll
    for (int q = 0; q < 4; q++) {
        int idx = tid + 256 * q;
        int cc  = idx >> 4;
        int c4  = idx & 15;
        int c   = c0 + cc;
        float4 v = make_float4(0.f, 0.f, 0.f, 0.f);
        if (c < nv) {
            int j = g_idx[b * SS + c];
            v = *(const float4*)(pe + ((size_t)j * BB + b) * DD + d0 + c4 * 4);
        }
        t[cc][c4 * 4 + 0] = v.x;
        t[cc][c4 * 4 + 1] = v.y;
        t[cc][c4 * 4 + 2] = v.z;
        t[cc][c4 * 4 + 3] = v.w;
    }
    __syncthreads();

#pragma unroll
    for (int q = 0; q < 4; q++) {
        int idx = tid + 256 * q;
        int dr  = idx >> 4;
        int c4  = idx & 15;
        __half h[4];
#pragma unroll
        for (int k = 0; k < 4; k++) h[k] = __float2half_rn(t[c4 * 4 + k][dr]);
        size_t dst = ((size_t)b * DD + d0 + dr) * SS + c0 + c4 * 4;
        *(uint2*)&g_peT[dst] = *(uint2*)h;
    }
}

// ---------------------------------------------------------------------------
// K3: compacted batched GEMM, fp16 mma.sync m16n8k16 (fp32 accum).
// Block tile 128x128, warp tile 64x32, 2-stage cp.async, 2 CTAs/SM.
// Inner loop: double-buffered register fragments — LDSM for ks+16 issued
// before the MMAs of ks, hiding the ~29cyc LDS latency inside one warp.
// ---------------------------------------------------------------------------
__global__ __launch_bounds__(256, 2) void gemm_fp16_kernel(float* __restrict__ out, int b0) {
    const int b  = b0 + blockIdx.z;
    const int ti = blockIdx.y * MT;
    const int td = blockIdx.x * NT;

    const int nI = g_nv[b];
    if (ti >= nI) return;
    const int kc = (nI + BK - 1) / BK;

    extern __shared__ __half sm[];
    const uint32_t sbase = smem_u32(sm);

    const int tid  = threadIdx.x;
    const int lane = tid & 31;
    const int warp = tid >> 5;
    const int wm   = warp & 1;        // 0..1 (M)
    const int wn   = warp >> 1;       // 0..3 (N)
    const int gid  = lane >> 2;
    const int tig  = lane & 3;

    const int lrow = lane & 7;
    const int lq   = lane >> 3;
    const int a_off = (lrow + 8 * (lq & 1)) * AST + 8 * (lq >> 1);
    const int b_off = (lrow + 8 * (lq >> 1)) * AST + 8 * (lq & 1);

    const __half* pA = g_probH + ((size_t)b * SS + ti) * SS;
    const __half* pB = g_peT   + ((size_t)b * DD + td) * SS;

    float acc[4][4][4];
#pragma unroll
    for (int mf = 0; mf < 4; mf++)
#pragma unroll
        for (int nf = 0; nf < 4; nf++)
#pragma unroll
            for (int r = 0; r < 4; r++) acc[mf][nf][r] = 0.0f;

    auto load_stage = [&](int kt) {
        const int j0 = kt * BK;
        const uint32_t base = sbase + (uint32_t)((kt & 1) * BUF_HALVES) * 2;
#pragma unroll
        for (int t = 0; t < 4; t++) {                 // A: 128 rows x 8 chunks
            int idx = tid + 256 * t;
            int row = idx >> 3, c = idx & 7;
            CP_ASYNC16(base + (uint32_t)(row * AST + c * 8) * 2,
                       pA + (size_t)row * SS + j0 + c * 8);
        }
#pragma unroll
        for (int t = 0; t < 4; t++) {                 // B: 128 rows x 8 chunks
            int idx = tid + 256 * t;
            int row = idx >> 3, c = idx & 7;
            CP_ASYNC16(base + (uint32_t)(A_HALVES + row * AST + c * 8) * 2,
                       pB + (size_t)row * SS + j0 + c * 8);
        }
        CP_COMMIT();
    };

    load_stage(0);

    uint32_t afr[2][4][4];
    uint32_t bfr[2][4][2];

    for (int kt = 0; kt < kc; kt++) {
        if (kt + 1 < kc) {
            load_stage(kt + 1);
            CP_WAIT(1);
        } else {
            CP_WAIT(0);
        }
        __syncthreads();

        const uint32_t abase = sbase + (uint32_t)((kt & 1) * BUF_HALVES) * 2;
        const uint32_t bbase = abase + (uint32_t)A_HALVES * 2;

        // Preload fragments for ks=0 into buffer 0.
#pragma unroll
        for (int mf = 0; mf < 4; mf++) {
            uint32_t ad = abase + (uint32_t)(((wm * 64 + mf * 16) * AST) + a_off) * 2;
            LDSM4(afr[0][mf][0], afr[0][mf][1], afr[0][mf][2], afr[0][mf][3], ad);
        }
#pragma unroll
        for (int np = 0; np < 2; np++) {
            uint32_t bd = bbase + (uint32_t)(((wn * 32 + np * 16) * AST) + b_off) * 2;
            LDSM4(bfr[0][2 * np][0], bfr[0][2 * np][1],
                  bfr[0][2 * np + 1][0], bfr[0][2 * np + 1][1], bd);
        }

#pragma unroll
        for (int kq = 0; kq < 4; kq++) {
            const int cur = kq & 1;
            const int nxt = cur ^ 1;
            if (kq < 3) {
                const int ksn = (kq + 1) * 16;
#pragma unroll
                for (int mf = 0; mf < 4; mf++) {
                    uint32_t ad = abase + (uint32_t)(((wm * 64 + mf * 16) * AST + ksn) + a_off) * 2;
                    LDSM4(afr[nxt][mf][0], afr[nxt][mf][1], afr[nxt][mf][2], afr[nxt][mf][3], ad);
                }
#pragma unroll
                for (int np = 0; np < 2; np++) {
                    uint32_t bd = bbase + (uint32_t)(((wn * 32 + np * 16) * AST + ksn) + b_off) * 2;
                    LDSM4(bfr[nxt][2 * np][0], bfr[nxt][2 * np][1],
                          bfr[nxt][2 * np + 1][0], bfr[nxt][2 * np + 1][1], bd);
                }
            }
#pragma unroll
            for (int mf = 0; mf < 4; mf++) {
#pragma unroll
                for (int nf = 0; nf < 4; nf++) {
                    asm volatile(
                        "mma.sync.aligned.m16n8k16.row.col.f32.f16.f16.f32 "
                        "{%0,%1,%2,%3}, {%4,%5,%6,%7}, {%8,%9}, {%0,%1,%2,%3};"
                        : "+f"(acc[mf][nf][0]), "+f"(acc[mf][nf][1]),
                          "+f"(acc[mf][nf][2]), "+f"(acc[mf][nf][3])
                        : "r"(afr[cur][mf][0]), "r"(afr[cur][mf][1]),
                          "r"(afr[cur][mf][2]), "r"(afr[cur][mf][3]),
                          "r"(bfr[cur][nf][0]), "r"(bfr[cur][nf][1]));
                }
            }
        }
        __syncthreads();
    }

    const int* idxp = g_idx + b * SS;
#pragma unroll
    for (int mf = 0; mf < 4; mf++) {
        int r0 = ti + wm * 64 + mf * 16 + gid;
        int r1 = r0 + 8;
        int ig0 = (r0 < nI) ? idxp[r0] : -1;
        int ig1 = (r1 < nI) ? idxp[r1] : -1;
#pragma unroll
        for (int nf = 0; nf < 4; nf++) {
            int col = td + wn * 32 + nf * 8 + tig * 2;
            if (ig0 >= 0)
                *(float2*)(out + (size_t)ig0 * (BB * DD) + (size_t)b * DD + col) =
                    make_float2(acc[mf][nf][0], acc[mf][nf][1]);
            if (ig1 >= 0)
                *(float2*)(out + (size_t)ig1 * (BB * DD) + (size_t)b * DD + col) =
                    make_float2(acc[mf][nf][2], acc[mf][nf][3]);
        }
    }
}

// ---------------------------------------------------------------------------
// Launch: 4-way per-batch-group pipeline (3 streams + 4 events, R10 budget).
// ---------------------------------------------------------------------------
extern "C" void kernel_launch(void* const* d_in, const int* in_sizes, int n_in,
                              void* d_out, int out_size) {
    const float* x    = (const float*)d_in[0];
    const float* pe   = (const float*)d_in[2];
    const void*  mask = d_in[3];
    const float* W    = (const float*)d_in[4];
    const float* bias = (const float*)d_in[5];
    float*       out  = (float*)d_out;

    cudaFuncSetAttribute(gemm_fp16_kernel,
                         cudaFuncAttributeMaxDynamicSharedMemorySize, GEMM_SMEM);

    cudaStream_t sx[3];
    cudaEvent_t  ev[3];
    cudaEvent_t  e0;
    cudaEventCreateWithFlags(&e0, cudaEventDisableTiming);
    for (int g = 0; g < 3; g++) {
        cudaStreamCreateWithFlags(&sx[g], cudaStreamNonBlocking);
        cudaEventCreateWithFlags(&ev[g], cudaEventDisableTiming);
    }

    mask_kernel<<<BB, 1024>>>(mask);
    cudaEventRecord(e0, 0);

    for (int g = 0; g < NGRP; g++) {
        int b0 = g * GB;
        cudaStream_t s = (g == 0) ? (cudaStream_t)0 : sx[g - 1];
        if (g != 0) cudaStreamWaitEvent(s, e0, 0);

        dim3 pgrid(SS, GB);
        probpred_kernel<<<pgrid, 256, 0, s>>>(x, W, bias, b0);

        dim3 g2(SS / 64, DD / 64, GB);
        gather_kernel<<<g2, 256, 0, s>>>(pe, b0);

        dim3 ggrid(DD / NT, SS / MT, GB);
        gemm_fp16_kernel<<<ggrid, 256, GEMM_SMEM, s>>>(out, b0);

        dim3 zgrid(SS / 4, GB);
        zerofill_kernel<<<zgrid, 1024, 0, s>>>(out, b0);

        if (g != 0) cudaEventRecord(ev[g - 1], s);
    }
    for (int g = 0; g < 3; g++) cudaStreamWaitEvent(0, ev[g], 0);

    cudaEventDestroy(e0);
    for (int g = 0; g < 3; g++) {
        cudaEventDestroy(ev[g]);
        cudaStreamDestroy(sx[g]);
    }
}